// round 4
// baseline (speedup 1.0000x reference)
#include <cuda_runtime.h>

// KANLinear: out[b,o] = x@base_weight + (basis(x) . spline_weight) * scaling[o]
// B=4096, IN=256, OUT=256, NB=66. Gaussian RBF basis is ~8-sparse (sigma == ~center
// spacing): window j0=floor(u)-3 .. +7 keeps all terms >= exp(-0.515*16)=2.6e-4 of peak.
//
// Stage 1: scaling[o] = mean_i max(scaler, 1e-7)
// Stage 2: per (b,i): window start j0 + 8 normalized gaussian weights -> scratch
// Stage 3: tiled accumulation: CTA = 64 b x 128 o, loop i, stage W_spline[i] slab
//          (66 x 128 fp32, stride-133 rows: conflict-free STS transpose AND
//          conflict-free per-k compute loads) in smem; 64 fp32 accumulators/thread.

#define BQ   4096
#define INF  256
#define OUTF 256
#define NB   66
#define WIN  8

// ---- device-global scratch (sanctioned: no allocation APIs allowed) ----
__device__ float  g_scale[OUTF];
__device__ float4 g_wbuf4[(size_t)INF * BQ * 2];   // [i][b][8 floats as 2x float4], 134 MB
__device__ int    g_jbuf[INF * BQ];                // [i][b]

// ---------------- Stage 1: output scaling vector ----------------
__global__ void kan_scale_kernel(const float* __restrict__ scaler) {
    int o = threadIdx.x;                 // 256 threads, 1 block
    float s = 0.f;
    #pragma unroll 8
    for (int i = 0; i < INF; ++i) s += fmaxf(scaler[i * OUTF + o], 1e-7f);
    g_scale[o] = s * (1.0f / INF);
}

// ---------------- Stage 2: windowed normalized basis weights ----------------
// Reference (fp32): x_c = clip(x,-1,1); x_norm = (x_c+1)/(2+1e-7)  [== /2.0 in fp32];
// x_scaled = x_norm*63; gi = clip(floor,0,61); lx = x_scaled-gi;
// bv_k = exp(-(lx - k/65)^2 * 66^2/2); normalize by (sum + 1e-7).
__global__ void kan_basis_kernel(const float* __restrict__ x) {
    int idx = blockIdx.x * 256 + threadIdx.x;       // idx = i*4096 + b  (2^20 total)
    int i = idx >> 12;
    int b = idx & (BQ - 1);

    float xv = x[(size_t)b * INF + i];
    float xc = fminf(fmaxf(xv, -1.0f), 1.0f);
    float xs = (xc + 1.0f) * 31.5f;                 // 63/(2+1e-7) == 31.5 exactly in fp32
    float gi = fminf(fmaxf(floorf(xs), 0.0f), 61.0f);
    float lx = xs - gi;                             // [0, 2]
    float u  = lx * 65.0f;                          // position in center units
    int j0 = (int)floorf(u) - 3;
    j0 = max(0, min(NB - WIN, j0));                 // clamp to [0, 58]

    float w[WIN];
    float s = 0.f;
    #pragma unroll
    for (int t = 0; t < WIN; ++t) {
        float d = lx - (float)(j0 + t) * (1.0f / 65.0f);
        float v = __expf(-2178.0f * d * d);         // 66^2/2 = 2178
        w[t] = v;
        s += v;
    }
    float inv = 1.0f / (s + 1e-7f);

    g_wbuf4[(size_t)idx * 2 + 0] = make_float4(w[0]*inv, w[1]*inv, w[2]*inv, w[3]*inv);
    g_wbuf4[(size_t)idx * 2 + 1] = make_float4(w[4]*inv, w[5]*inv, w[6]*inv, w[7]*inv);
    g_jbuf[idx] = j0;
}

// ---------------- Stage 3: main fused accumulation ----------------
// Grid: 128 CTAs = 64 b-tiles x 2 o-halves. CTA: 256 threads (8 warps).
// Warp w owns b's [8w, 8w+8); lane owns o = lane + {0,32,64,96} within the o-half.
__global__ __launch_bounds__(256) void kan_main_kernel(
        const float* __restrict__ x,
        const float* __restrict__ bw,
        const float* __restrict__ sw,
        float* __restrict__ out) {
    __shared__ float  s_slab[NB][133];   // stride 133 (odd*... 5 mod 32): conflict-free
    __shared__ float4 s_w4[128];         // 64 b x 8 weights
    __shared__ int    s_j[64];
    __shared__ float  s_x[64];
    __shared__ float  s_bw[128];
    __shared__ float  s_scale[128];

    const int tid  = threadIdx.x;
    const int bt   = blockIdx.x >> 1;
    const int os   = blockIdx.x & 1;
    const int b0   = bt * 64;
    const int o0   = os * 128;
    const int warp = tid >> 5;
    const int lane = tid & 31;

    if (tid < 128) s_scale[tid] = g_scale[o0 + tid];

    float accB[32], accS[32];
    #pragma unroll
    for (int q = 0; q < 32; ++q) { accB[q] = 0.f; accS[q] = 0.f; }

    for (int i = 0; i < INF; ++i) {
        __syncthreads();   // previous iteration's reads done before restaging

        // Stage W_spline[i, o0:o0+128, 0:66] -> transposed slab s_slab[k][o].
        // Gmem reads fully coalesced (contiguous range); STS hits distinct banks
        // (consecutive k -> bank step 5, gcd(5,32)=1).
        const float* src = sw + ((size_t)i * OUTF + o0) * NB;
        #pragma unroll
        for (int r = 0; r < 33; ++r) {               // 33*256 = 8448 = 128*66
            int idx = tid + (r << 8);
            float v = src[idx];
            int ol = idx / NB;
            int k  = idx - ol * NB;
            s_slab[k][ol] = v;
        }
        if (tid < 128) {
            s_w4[tid] = g_wbuf4[((size_t)i * BQ + b0) * 2 + tid];
            s_bw[tid] = bw[i * OUTF + o0 + tid];
        }
        if (tid < 64) {
            s_j[tid] = g_jbuf[i * BQ + b0 + tid];
            s_x[tid] = x[(size_t)(b0 + tid) * INF + i];
        }
        __syncthreads();

        const float bw0 = s_bw[lane];
        const float bw1 = s_bw[lane + 32];
        const float bw2 = s_bw[lane + 64];
        const float bw3 = s_bw[lane + 96];
        const float* wflat = (const float*)s_w4;

        #pragma unroll
        for (int bb = 0; bb < 8; ++bb) {
            const int b  = (warp << 3) + bb;
            const float xv = s_x[b];
            const int j0 = s_j[b];
            accB[bb*4+0] += xv * bw0;
            accB[bb*4+1] += xv * bw1;
            accB[bb*4+2] += xv * bw2;
            accB[bb*4+3] += xv * bw3;
            #pragma unroll
            for (int t = 0; t < WIN; ++t) {
                const float wt = wflat[b * WIN + t];           // warp-broadcast LDS
                const float* sr = s_slab[j0 + t];              // lanes hit 32 banks
                accS[bb*4+0] += wt * sr[lane];
                accS[bb*4+1] += wt * sr[lane + 32];
                accS[bb*4+2] += wt * sr[lane + 64];
                accS[bb*4+3] += wt * sr[lane + 96];
            }
        }
    }

    // Epilogue: out = base + spline * scaling[o]; coalesced 128B stores.
    #pragma unroll
    for (int bb = 0; bb < 8; ++bb) {
        const int b = b0 + (warp << 3) + bb;
        #pragma unroll
        for (int m = 0; m < 4; ++m) {
            const int o = lane + 32 * m;
            out[(size_t)b * OUTF + o0 + o] = accB[bb*4+m] + accS[bb*4+m] * s_scale[o];
        }
    }
}

extern "C" void kernel_launch(void* const* d_in, const int* in_sizes, int n_in,
                              void* d_out, int out_size) {
    const float* x  = (const float*)d_in[0];   // [4096, 256]
    const float* bw = (const float*)d_in[1];   // [256, 256]
    const float* sw = (const float*)d_in[2];   // [256, 256, 66]
    const float* sc = (const float*)d_in[3];   // [256, 256]
    float* out = (float*)d_out;                // [4096, 256] fp32

    kan_scale_kernel<<<1, 256>>>(sc);
    kan_basis_kernel<<<(BQ * INF) / 256, 256>>>(x);
    kan_main_kernel<<<128, 256>>>(x, bw, sw, out);
}

// round 6
// speedup vs baseline: 5.2060x; 5.2060x over previous
#include <cuda_runtime.h>
#include <cuda_fp16.h>
#include <cstdint>

// ============================================================================
// KANLinear:
//   out[b,o] = x@Wb  (fp32 CUDA-core GEMM, plain store)
//            + basis(x)[b,:] @ W2[:,o]  (fp16 mma.sync GEMM, split-K, red.add)
// W2[o][i*66+kk] = spline_weight[i][o][kk] * scaling[o]
// basis row = 8-wide windowed gaussian (validated R3, rel 2.5e-5 vs dense).
// tcgen05 is rejected by this harness's ptxas target (sm_103, no 'a'), so the
// tensor work goes through HMMA mma.sync.m16n8k16.
// ============================================================================

#define BQ    4096
#define INF   256
#define OUTF  256
#define NB    66
#define WIN   8
#define KTOT  (INF * NB)          // 16896
#define KTILE 64                  // halfs per chunk (128 bytes)
#define KSPLIT 4
#define KPS   (KTOT / KSPLIT)     // 4224
#define CHUNKS (KPS / KTILE)      // 66
#define STAGES 3
#define MT 128
#define NT 256
#define A_STAGE_B (MT * KTILE * 2)   // 16384
#define B_STAGE_B (NT * KTILE * 2)   // 32768
#define STAGE_B   (A_STAGE_B + B_STAGE_B)  // 49152

// ---- device-global scratch (static; no allocation APIs) ----
__device__ float g_scale[OUTF];
__device__ __align__(256) __half g_A [(size_t)BQ   * KTOT];   // [b][k] 138 MB
__device__ __align__(256) __half g_W2[(size_t)OUTF * KTOT];   // [o][k] 8.6 MB

// ============================ PTX helpers ===================================
__device__ __forceinline__ uint32_t smem_u32(const void* p) {
    uint32_t a;
    asm("{ .reg .u64 t; cvta.to.shared.u64 t, %1; cvt.u32.u64 %0, t; }"
        : "=r"(a) : "l"(p));
    return a;
}
#define CP_ASYNC16(dst, src) \
    asm volatile("cp.async.cg.shared.global [%0], [%1], 16;" :: "r"(dst), "l"(src))
#define CP_COMMIT()  asm volatile("cp.async.commit_group;" ::: "memory")
#define CP_WAITG(n)  asm volatile("cp.async.wait_group %0;" :: "n"(n) : "memory")

#define LDSM_X4(r0, r1, r2, r3, addr) \
    asm volatile("ldmatrix.sync.aligned.m8n8.x4.shared.b16 {%0,%1,%2,%3}, [%4];" \
                 : "=r"(r0), "=r"(r1), "=r"(r2), "=r"(r3) : "r"(addr))

#define MMA16816(d, a, b) \
    asm volatile("mma.sync.aligned.m16n8k16.row.col.f32.f16.f16.f32 " \
                 "{%0,%1,%2,%3}, {%4,%5,%6,%7}, {%8,%9}, {%0,%1,%2,%3};" \
                 : "+f"((d)[0]), "+f"((d)[1]), "+f"((d)[2]), "+f"((d)[3]) \
                 : "r"((a)[0]), "r"((a)[1]), "r"((a)[2]), "r"((a)[3]), \
                   "r"((b)[0]), "r"((b)[1]))

// ==================== Stage 1: scaling vector ===============================
__global__ __launch_bounds__(256) void kan_scale_kernel(const float* __restrict__ sc) {
    int w = (blockIdx.x * 256 + threadIdx.x) >> 5;   // o index; grid 32 x 256
    int lane = threadIdx.x & 31;
    float s = 0.f;
    #pragma unroll
    for (int r = 0; r < 8; ++r) s += fmaxf(sc[(lane + r * 32) * OUTF + w], 1e-7f);
    #pragma unroll
    for (int o = 16; o; o >>= 1) s += __shfl_xor_sync(0xFFFFFFFFu, s, o);
    if (lane == 0) g_scale[w] = s * (1.0f / INF);
}

// ============ Stage 2: W2[o][i*66+kk] = fp16(sw[i][o][kk] * scale[o]) =======
__global__ __launch_bounds__(256) void kan_w2_kernel(const float* __restrict__ sw) {
    __shared__ __half s_row[KTOT];                   // 33 KB
    const int o = blockIdx.x;
    const int i = threadIdx.x;
    const float s = g_scale[o];
    const float2* src = (const float2*)(sw + ((size_t)i * OUTF + o) * NB);
    __half* dst = s_row + i * NB;
    #pragma unroll
    for (int q = 0; q < NB / 2; ++q) {
        float2 v = src[q];
        dst[2 * q]     = __float2half(v.x * s);
        dst[2 * q + 1] = __float2half(v.y * s);
    }
    __syncthreads();
    uint4* gout = (uint4*)(g_W2 + (size_t)o * KTOT);
    const uint4* s4 = (const uint4*)s_row;
    for (int idx = threadIdx.x; idx < KTOT / 8; idx += 256) gout[idx] = s4[idx];
}

// ====== Stage 3: basis matrix g_A[b][k], fp16, smem-staged coalesced ========
__global__ __launch_bounds__(256) void kan_basis_kernel(const float* __restrict__ x) {
    __shared__ __half s_row[KTOT];                   // 33 KB
    const int b = blockIdx.x;
    const int i = threadIdx.x;

    uint4* s4 = (uint4*)s_row;
    uint4 z = make_uint4(0u, 0u, 0u, 0u);
    for (int idx = i; idx < KTOT / 8; idx += 256) s4[idx] = z;

    float xv = x[(size_t)b * INF + i];
    float xc = fminf(fmaxf(xv, -1.0f), 1.0f);
    float xs = (xc + 1.0f) * 31.5f;                  // 63/(2+1e-7) == 31.5 in fp32
    float gi = fminf(fmaxf(floorf(xs), 0.0f), 61.0f);
    float lx = xs - gi;
    float u  = lx * 65.0f;
    int j0 = (int)floorf(u) - 3;
    j0 = max(0, min(NB - WIN, j0));

    float w[WIN], sm = 0.f;
    #pragma unroll
    for (int t = 0; t < WIN; ++t) {
        float d = lx - (float)(j0 + t) * (1.0f / 65.0f);
        float v = __expf(-2178.0f * d * d);          // 66^2/2
        w[t] = v; sm += v;
    }
    float inv = 1.0f / (sm + 1e-7f);

    __syncthreads();
    __half* wr = s_row + i * NB + j0;
    #pragma unroll
    for (int t = 0; t < WIN; ++t) wr[t] = __float2half(w[t] * inv);
    __syncthreads();

    uint4* gout = (uint4*)(g_A + (size_t)b * KTOT);
    for (int idx = i; idx < KTOT / 8; idx += 256) gout[idx] = s4[idx];
}

// ================= Stage 4: base GEMM fp32 (out = x @ Wb) ===================
__global__ __launch_bounds__(256) void kan_base_gemm(const float* __restrict__ x,
                                                     const float* __restrict__ bw,
                                                     float* __restrict__ out) {
    __shared__ float As[16 * 68];
    __shared__ float Bs[16 * 68];
    const int tid = threadIdx.x;
    const int m0 = blockIdx.x * 64;
    const int n0 = blockIdx.y * 64;
    const int tx = tid & 15, ty = tid >> 4;
    const int am = tid >> 2, ak = tid & 3;
    const int bk = tid >> 4, bn = tid & 15;

    float acc[4][4];
    #pragma unroll
    for (int a = 0; a < 4; ++a)
        #pragma unroll
        for (int c = 0; c < 4; ++c) acc[a][c] = 0.f;

    float4 pa = *(const float4*)(x  + (size_t)(m0 + am) * INF + ak * 4);
    float4 pb = *(const float4*)(bw + (size_t)bk * OUTF + n0 + bn * 4);

    for (int kc = 0; kc < 16; ++kc) {
        As[(ak*4+0)*68 + am] = pa.x; As[(ak*4+1)*68 + am] = pa.y;
        As[(ak*4+2)*68 + am] = pa.z; As[(ak*4+3)*68 + am] = pa.w;
        *(float4*)(Bs + bk * 68 + bn * 4) = pb;
        __syncthreads();
        if (kc < 15) {
            pa = *(const float4*)(x  + (size_t)(m0 + am) * INF + (kc + 1) * 16 + ak * 4);
            pb = *(const float4*)(bw + (size_t)((kc + 1) * 16 + bk) * OUTF + n0 + bn * 4);
        }
        #pragma unroll
        for (int k = 0; k < 16; ++k) {
            float4 a4 = *(const float4*)(As + k * 68 + ty * 4);
            float4 b4 = *(const float4*)(Bs + k * 68 + tx * 4);
            float av[4] = {a4.x, a4.y, a4.z, a4.w};
            float bv[4] = {b4.x, b4.y, b4.z, b4.w};
            #pragma unroll
            for (int a = 0; a < 4; ++a)
                #pragma unroll
                for (int c = 0; c < 4; ++c) acc[a][c] += av[a] * bv[c];
        }
        __syncthreads();
    }
    #pragma unroll
    for (int a = 0; a < 4; ++a) {
        float4 v = make_float4(acc[a][0], acc[a][1], acc[a][2], acc[a][3]);
        *(float4*)(out + (size_t)(m0 + ty * 4 + a) * OUTF + n0 + tx * 4) = v;
    }
}

// ====== Stage 5: spline GEMM, mma.sync fp16, split-K, out += A @ W2^T =======
// Grid (32, 4): 32 m-tiles x 4 k-splits. 512 threads = 16 warps (4m x 4n).
// Warp tile 32x64. 3-stage cp.async pipeline, SW128-xor-swizzled smem.
__global__ __launch_bounds__(512, 1) void kan_spline_gemm(float* __restrict__ out) {
    extern __shared__ __align__(256) char dsm[];     // STAGES * 48 KB
    const int tid  = threadIdx.x;
    const int wid  = tid >> 5;
    const int lane = tid & 31;
    const int m0 = blockIdx.x * MT;
    const int k0 = blockIdx.y * KPS;                 // in halfs
    const int warp_m = wid & 3;
    const int warp_n = wid >> 2;
    const uint32_t sbase = smem_u32(dsm);

    const __half* gA = g_A  + (size_t)m0 * KTOT + k0;
    const __half* gB = g_W2 + k0;

    // cp.async mapping: 16B chunk q -> row = q>>3, c = q&7; swizzled dst.
    uint32_t aOff[2]; size_t aSrc[2];
    #pragma unroll
    for (int j = 0; j < 2; ++j) {
        int q = tid + 512 * j, r = q >> 3, c = q & 7;
        aOff[j] = (uint32_t)r * 128 + ((uint32_t)(c ^ (r & 7)) << 4);
        aSrc[j] = (size_t)r * KTOT + c * 8;
    }
    uint32_t bOff[4]; size_t bSrc[4];
    #pragma unroll
    for (int j = 0; j < 4; ++j) {
        int q = tid + 512 * j, r = q >> 3, c = q & 7;
        bOff[j] = (uint32_t)r * 128 + ((uint32_t)(c ^ (r & 7)) << 4);
        bSrc[j] = (size_t)r * KTOT + c * 8;
    }

    float acc[2][8][4];
    #pragma unroll
    for (int a = 0; a < 2; ++a)
        #pragma unroll
        for (int bn = 0; bn < 8; ++bn)
            #pragma unroll
            for (int t = 0; t < 4; ++t) acc[a][bn][t] = 0.f;

    // ldmatrix lane bases (row part; column xor varies per k-step)
    const int arow = warp_m * 32 + (lane & 15);      // + a*16 (same &7)
    const int asub = lane >> 4;
    const int axor = arow & 7;
    const int bg   = lane >> 3;
    const int brow_in = ((bg >> 1) << 3) + (lane & 7);   // 0..15
    const int bsub = bg & 1;
    const int bxor = lane & 7;                       // == brow & 7

    // prefetch chunks 0,1
    #pragma unroll
    for (int p = 0; p < 2; ++p) {
        uint32_t sb = sbase + p * STAGE_B;
        int kh = p * KTILE;
        #pragma unroll
        for (int j = 0; j < 2; ++j) CP_ASYNC16(sb + aOff[j], gA + aSrc[j] + kh);
        #pragma unroll
        for (int j = 0; j < 4; ++j) CP_ASYNC16(sb + A_STAGE_B + bOff[j], gB + bSrc[j] + kh);
        CP_COMMIT();
    }

    for (int c = 0; c < CHUNKS; ++c) {
        const int s = c % STAGES;
        if (c + 2 < CHUNKS) {
            const int s2 = (c + 2) % STAGES;
            uint32_t sb = sbase + s2 * STAGE_B;
            int kh = (c + 2) * KTILE;
            #pragma unroll
            for (int j = 0; j < 2; ++j) CP_ASYNC16(sb + aOff[j], gA + aSrc[j] + kh);
            #pragma unroll
            for (int j = 0; j < 4; ++j) CP_ASYNC16(sb + A_STAGE_B + bOff[j], gB + bSrc[j] + kh);
            CP_COMMIT();
            CP_WAITG(2);
        } else if (c + 1 < CHUNKS) {
            CP_WAITG(1);
        } else {
            CP_WAITG(0);
        }
        __syncthreads();

        const uint32_t As = sbase + s * STAGE_B;
        const uint32_t Bs = As + A_STAGE_B;
        const uint32_t aBase = As + (uint32_t)arow * 128;
        const uint32_t bBase = Bs + (uint32_t)(warp_n * 64 + brow_in) * 128;

        #pragma unroll
        for (int ks = 0; ks < 4; ++ks) {
            uint32_t af[2][4];
            const uint32_t ax = (uint32_t)(((ks * 2 + asub) ^ axor) << 4);
            LDSM_X4(af[0][0], af[0][1], af[0][2], af[0][3], aBase + ax);
            LDSM_X4(af[1][0], af[1][1], af[1][2], af[1][3], aBase + 2048 + ax);

            uint32_t bf[8][2];
            const uint32_t bx = (uint32_t)(((ks * 2 + bsub) ^ bxor) << 4);
            #pragma unroll
            for (int p = 0; p < 4; ++p) {
                LDSM_X4(bf[2*p][0], bf[2*p][1], bf[2*p+1][0], bf[2*p+1][1],
                        bBase + (uint32_t)p * 2048 + bx);
            }
            #pragma unroll
            for (int a = 0; a < 2; ++a)
                #pragma unroll
                for (int bn = 0; bn < 8; ++bn)
                    MMA16816(acc[a][bn], af[a], bf[bn]);
        }
        __syncthreads();
    }

    // Epilogue: red.add partials onto out (base result already there).
    #pragma unroll
    for (int a = 0; a < 2; ++a) {
        const int row = m0 + warp_m * 32 + a * 16 + (lane >> 2);
        #pragma unroll
        for (int bn = 0; bn < 8; ++bn) {
            const int col = warp_n * 64 + bn * 8 + (lane & 3) * 2;
            float* p0 = out + (size_t)row * OUTF + col;
            atomicAdd(p0,              acc[a][bn][0]);
            atomicAdd(p0 + 1,          acc[a][bn][1]);
            atomicAdd(p0 + 8 * OUTF,     acc[a][bn][2]);
            atomicAdd(p0 + 8 * OUTF + 1, acc[a][bn][3]);
        }
    }
}

// ============================================================================
extern "C" void kernel_launch(void* const* d_in, const int* in_sizes, int n_in,
                              void* d_out, int out_size) {
    const float* x  = (const float*)d_in[0];   // [4096, 256]
    const float* bw = (const float*)d_in[1];   // [256, 256]
    const float* sw = (const float*)d_in[2];   // [256, 256, 66]
    const float* sc = (const float*)d_in[3];   // [256, 256]
    float* out = (float*)d_out;                // [4096, 256] fp32

    static bool attr_done = false;
    if (!attr_done) {
        cudaFuncSetAttribute(kan_spline_gemm,
                             cudaFuncAttributeMaxDynamicSharedMemorySize,
                             STAGES * STAGE_B);
        attr_done = true;
    }

    kan_scale_kernel<<<32, 256>>>(sc);
    kan_w2_kernel<<<OUTF, 256>>>(sw);
    kan_basis_kernel<<<BQ, 256>>>(x);
    kan_base_gemm<<<dim3(BQ / 64, OUTF / 64), 256>>>(x, bw, out);
    kan_spline_gemm<<<dim3(BQ / MT, KSPLIT), 512, STAGES * STAGE_B>>>(out);
}

// round 7
// speedup vs baseline: 5.4938x; 1.0553x over previous
#include <cuda_runtime.h>
#include <cuda_fp16.h>
#include <cstdint>

// ============================================================================
// KANLinear, fully fused GEMM formulation (HMMA mma.sync; tcgen05 rejected by
// this harness's ptxas target sm_103):
//   out[b,o] = [ basis(x) | fp16(x) ] @ [ W2 | Wb ]^T      (K' = 16896 + 256)
// W2[o][i*66+kk] = spline_weight[i][o][kk] * scaling[o];  Wb appended raw.
// basis rows are 8-sparse windows (g_win: 8 fp16 + j0/byte), expanded into
// the GEMM's SMEM A-stage on the fly (no dense A matrix in DRAM).
// ============================================================================

#define BQ     4096
#define INF    256
#define OUTF   256
#define NB     66
#define WIN    8
#define KSPL   (INF * NB)        // 16896 spline K
#define KTOT2  (KSPL + INF)      // 17152 with base section
#define KTILE  64                // halfs per chunk (128 B rows)
#define KSPLIT 4
#define SCH    66                // spline chunks per split (66*64 = 4224 = 64 i's)
#define NCH    67                // + 1 base chunk
#define MT     128
#define NT     256
#define A_STAGE_B (MT * KTILE * 2)            // 16384
#define B_STAGE_B (NT * KTILE * 2)            // 32768
#define STAGE_B   (A_STAGE_B + B_STAGE_B)     // 49152, 3 stages = 144 KB

// ---- device-global scratch (static; no allocation APIs) ----
__device__ float g_scale[OUTF];
__device__ __align__(256) uint4   g_win[(size_t)INF * BQ];   // [i][b] 8 fp16, 16.8 MB
__device__ uint8_t                g_j0 [(size_t)INF * BQ];   // [i][b] window start
__device__ __align__(256) __half  g_W2[(size_t)OUTF * KTOT2];// [o][k'] 8.8 MB

// ============================ PTX helpers ===================================
__device__ __forceinline__ uint32_t smem_u32(const void* p) {
    uint32_t a;
    asm("{ .reg .u64 t; cvta.to.shared.u64 t, %1; cvt.u32.u64 %0, t; }"
        : "=r"(a) : "l"(p));
    return a;
}
#define CP_ASYNC16(dst, src) \
    asm volatile("cp.async.cg.shared.global [%0], [%1], 16;" :: "r"(dst), "l"(src))
#define CP_COMMIT()  asm volatile("cp.async.commit_group;" ::: "memory")
#define CP_WAITG(n)  asm volatile("cp.async.wait_group %0;" :: "n"(n) : "memory")

#define LDSM_X4(r0, r1, r2, r3, addr) \
    asm volatile("ldmatrix.sync.aligned.m8n8.x4.shared.b16 {%0,%1,%2,%3}, [%4];" \
                 : "=r"(r0), "=r"(r1), "=r"(r2), "=r"(r3) : "r"(addr))

#define MMA16816(d, a, b) \
    asm volatile("mma.sync.aligned.m16n8k16.row.col.f32.f16.f16.f32 " \
                 "{%0,%1,%2,%3}, {%4,%5,%6,%7}, {%8,%9}, {%0,%1,%2,%3};" \
                 : "+f"((d)[0]), "+f"((d)[1]), "+f"((d)[2]), "+f"((d)[3]) \
                 : "r"((a)[0]), "r"((a)[1]), "r"((a)[2]), "r"((a)[3]), \
                   "r"((b)[0]), "r"((b)[1]))

__device__ __forceinline__ uint32_t pk2(float a, float b) {
    __half2 h = __floats2half2_rn(a, b);
    return *reinterpret_cast<uint32_t*>(&h);
}

// ==================== Stage 1: scaling vector ===============================
__global__ __launch_bounds__(256) void kan_scale_kernel(const float* __restrict__ sc) {
    int w = (blockIdx.x * 256 + threadIdx.x) >> 5;   // o index; grid 32 x 256
    int lane = threadIdx.x & 31;
    float s = 0.f;
    #pragma unroll
    for (int r = 0; r < 8; ++r) s += fmaxf(sc[(lane + r * 32) * OUTF + w], 1e-7f);
    #pragma unroll
    for (int o = 16; o; o >>= 1) s += __shfl_xor_sync(0xFFFFFFFFu, s, o);
    if (lane == 0) g_scale[w] = s * (1.0f / INF);
}

// == Stage 2: g_W2[o][i*66+kk] = fp16(sw[i][o][kk]*scale[o]); base appended ==
__global__ __launch_bounds__(256) void kan_w2_kernel(const float* __restrict__ sw,
                                                     const float* __restrict__ bw) {
    __shared__ __half s_row[KTOT2];                  // 33.5 KB
    const int o = blockIdx.x;
    const int i = threadIdx.x;
    const float s = g_scale[o];
    const float2* src = (const float2*)(sw + ((size_t)i * OUTF + o) * NB);
    __half* dst = s_row + i * NB;
    #pragma unroll
    for (int q = 0; q < NB / 2; ++q) {
        float2 v = src[q];
        dst[2 * q]     = __float2half(v.x * s);
        dst[2 * q + 1] = __float2half(v.y * s);
    }
    s_row[KSPL + i] = __float2half(bw[(size_t)i * OUTF + o]);   // base section
    __syncthreads();
    uint4* gout = (uint4*)(g_W2 + (size_t)o * KTOT2);
    const uint4* s4 = (const uint4*)s_row;
    for (int idx = threadIdx.x; idx < KTOT2 / 8; idx += 256) gout[idx] = s4[idx];
}

// ======== Stage 3: window kernel -> g_win[i][b] (8 fp16) + g_j0[i][b] =======
// Same proven window math as R3/R5 (rel 2.5e-5 vs dense reference).
__global__ __launch_bounds__(256) void kan_win_kernel(const float* __restrict__ x) {
    __shared__ float sx[64][65];
    const int b0 = blockIdx.x * 64;
    const int i0 = blockIdx.y * 64;
    const int t  = threadIdx.x;
    {   // coalesced 64x64 x-tile load, transposed access later via smem
        int r = t >> 2, seg = t & 3;
        const float4* src = (const float4*)(x + (size_t)(b0 + r) * INF + i0 + seg * 16);
        #pragma unroll
        for (int q = 0; q < 4; ++q) {
            float4 v = src[q];
            sx[r][seg*16 + q*4 + 0] = v.x; sx[r][seg*16 + q*4 + 1] = v.y;
            sx[r][seg*16 + q*4 + 2] = v.z; sx[r][seg*16 + q*4 + 3] = v.w;
        }
    }
    __syncthreads();
    #pragma unroll 1
    for (int wl = 0; wl < 16; ++wl) {
        const int il = wl * 4 + (t >> 6);
        const int bl = t & 63;
        float xv = sx[bl][il];
        float xc = fminf(fmaxf(xv, -1.0f), 1.0f);
        float xs = (xc + 1.0f) * 31.5f;              // 63/(2+1e-7) == 31.5 in fp32
        float gi = fminf(fmaxf(floorf(xs), 0.0f), 61.0f);
        float lx = xs - gi;
        float u  = lx * 65.0f;
        int j0 = (int)floorf(u) - 3;
        j0 = max(0, min(NB - WIN, j0));

        float w[WIN], sm = 0.f;
        #pragma unroll
        for (int tt = 0; tt < WIN; ++tt) {
            float d = lx - (float)(j0 + tt) * (1.0f / 65.0f);
            float v = __expf(-2178.0f * d * d);      // 66^2/2
            w[tt] = v; sm += v;
        }
        float inv = 1.0f / (sm + 1e-7f);

        uint4 pk;
        pk.x = pk2(w[0]*inv, w[1]*inv);
        pk.y = pk2(w[2]*inv, w[3]*inv);
        pk.z = pk2(w[4]*inv, w[5]*inv);
        pk.w = pk2(w[6]*inv, w[7]*inv);
        const size_t gi2 = (size_t)(i0 + il) * BQ + b0 + bl;
        g_win[gi2] = pk;
        g_j0[gi2]  = (uint8_t)j0;
    }
}

// ======= Stage 4: fused GEMM (spline + base), split-K, in-SMEM A gen ========
// Grid (32, 4): m-tiles x k-splits. 512 thr = 16 warps (4m x 4n), warp 32x64.
__global__ __launch_bounds__(512, 1) void kan_spline_gemm(const float* __restrict__ x,
                                                          float* __restrict__ out) {
    extern __shared__ __align__(256) char dsm[];     // 3 * 48 KB
    const int tid  = threadIdx.x;
    const int wid  = tid >> 5;
    const int lane = tid & 31;
    const int m0 = blockIdx.x * MT;
    const int split = blockIdx.y;
    const int k0 = split * (SCH * KTILE);            // 4224*split
    const int warp_m = wid & 3;
    const int warp_n = wid >> 2;
    const uint32_t sbase = smem_u32(dsm);

    // B cp.async mapping: thread covers 4 16B chunks per stage
    uint32_t bOff[4]; size_t bRow[4]; int bCol[4];
    #pragma unroll
    for (int j = 0; j < 4; ++j) {
        int q = tid + 512 * j, r = q >> 3, c = q & 7;
        bOff[j] = A_STAGE_B + (uint32_t)r * 128 + ((uint32_t)(c ^ (r & 7)) << 4);
        bRow[j] = (size_t)r * KTOT2;
        bCol[j] = c * 8;
    }

    float acc[2][8][4];
    #pragma unroll
    for (int a = 0; a < 2; ++a)
        #pragma unroll
        for (int bn = 0; bn < 8; ++bn)
            #pragma unroll
            for (int q = 0; q < 4; ++q) acc[a][bn][q] = 0.f;

    // ldmatrix lane bases (proven mapping from R5)
    const int arow = warp_m * 32 + (lane & 15);
    const int asub = lane >> 4;
    const int axor = arow & 7;
    const int bg   = lane >> 3;
    const int brow_in = ((bg >> 1) << 3) + (lane & 7);
    const int bsub = bg & 1;
    const int bxor = lane & 7;

    // A-generation registers (loaded at prefetch time, stored after MMA)
    uint4  wreg;  int wvalid = 0, wb = 0, wkb = 0;
    float4 xA, xB, xC, xD;  int isbase = 0;

    for (int c = -2; c < NCH; ++c) {
        const int cp = c + 2;
        const bool has = cp < NCH;
        const int sp = cp % 3;
        if (has) {
            // ---- B prefetch for chunk cp ----
            const size_t koff = (cp < SCH) ? (size_t)(k0 + cp * KTILE)
                                           : (size_t)(KSPL + split * KTILE);
            const uint32_t sb = sbase + (uint32_t)sp * STAGE_B;
            #pragma unroll
            for (int j = 0; j < 4; ++j)
                CP_ASYNC16(sb + bOff[j], g_W2 + bRow[j] + koff + bCol[j]);
            CP_COMMIT();
            // ---- A-gen loads for chunk cp ----
            wvalid = 0; isbase = 0;
            if (cp < SCH) {
                if (tid < 256) {
                    const int kglob = k0 + cp * KTILE;
                    const int i_first = kglob / NB;
                    const int i_last  = (kglob + KTILE - 1) / NB;
                    const int i = i_first + (tid >> 7);
                    if (i <= i_last && i < INF) {
                        wb = tid & 127;
                        const size_t gi2 = (size_t)i * BQ + m0 + wb;
                        wreg = g_win[gi2];
                        wkb  = i * NB + (int)g_j0[gi2] - kglob;
                        wvalid = 1;
                    }
                }
            } else {
                isbase = 1;
                const int r = tid >> 2, seg = tid & 3;
                const float4* xr = (const float4*)(x + (size_t)(m0 + r) * INF
                                                   + split * KTILE + seg * 16);
                xA = xr[0]; xB = xr[1]; xC = xr[2]; xD = xr[3];
            }
        }
        if (c < 0) {
            // prologue: stage not yet read by anyone; fill immediately
            char* st = dsm + (size_t)sp * STAGE_B;
            if (cp < SCH) {
                uint4 z = make_uint4(0u, 0u, 0u, 0u);
                *(uint4*)(st + tid * 16) = z;
                *(uint4*)(st + 8192 + tid * 16) = z;
                __syncthreads();                      // zeros before scatter
                if (wvalid) {
                    const __half* wh = (const __half*)&wreg;
                    #pragma unroll
                    for (int t = 0; t < WIN; ++t) {
                        int k = wkb + t;
                        if ((unsigned)k < (unsigned)KTILE)
                            *(__half*)(st + wb * 128
                                       + ((((unsigned)k >> 3) ^ (wb & 7)) << 4)
                                       + ((k & 7) << 1)) = wh[t];
                    }
                }
            }
            continue;
        }
        if (has) { CP_WAITG(2); } else if (c == NCH - 2) { CP_WAITG(1); }
        else { CP_WAITG(0); }
        __syncthreads();          // chunk c ready; all reads of stage sp done

        if (has && cp < SCH) {    // zero next A-stage (safe after sync)
            char* st = dsm + (size_t)sp * STAGE_B;
            uint4 z = make_uint4(0u, 0u, 0u, 0u);
            *(uint4*)(st + tid * 16) = z;
            *(uint4*)(st + 8192 + tid * 16) = z;
        }

        // ---- MMA on chunk c ----
        {
            const int s = c % 3;
            const uint32_t As = sbase + (uint32_t)s * STAGE_B;
            const uint32_t Bs = As + A_STAGE_B;
            const uint32_t aBase = As + (uint32_t)arow * 128;
            const uint32_t bBase = Bs + (uint32_t)(warp_n * 64 + brow_in) * 128;
            #pragma unroll
            for (int ks = 0; ks < 4; ++ks) {
                uint32_t af[2][4];
                const uint32_t ax = (uint32_t)(((ks * 2 + asub) ^ axor) << 4);
                LDSM_X4(af[0][0], af[0][1], af[0][2], af[0][3], aBase + ax);
                LDSM_X4(af[1][0], af[1][1], af[1][2], af[1][3], aBase + 2048 + ax);
                uint32_t bf[8][2];
                const uint32_t bx = (uint32_t)(((ks * 2 + bsub) ^ bxor) << 4);
                #pragma unroll
                for (int p = 0; p < 4; ++p)
                    LDSM_X4(bf[2*p][0], bf[2*p][1], bf[2*p+1][0], bf[2*p+1][1],
                            bBase + (uint32_t)p * 2048 + bx);
                #pragma unroll
                for (int a = 0; a < 2; ++a)
                    #pragma unroll
                    for (int bn = 0; bn < 8; ++bn)
                        MMA16816(acc[a][bn], af[a], bf[bn]);
            }
        }
        __syncthreads();          // zeros done + MMA reads done before scatter

        if (has) {                // ---- store A-gen into stage sp ----
            char* st = dsm + (size_t)sp * STAGE_B;
            if (isbase) {
                const int r = tid >> 2, seg = tid & 3;
                uint4 v0, v1;
                v0.x = pk2(xA.x, xA.y); v0.y = pk2(xA.z, xA.w);
                v0.z = pk2(xB.x, xB.y); v0.w = pk2(xB.z, xB.w);
                v1.x = pk2(xC.x, xC.y); v1.y = pk2(xC.z, xC.w);
                v1.z = pk2(xD.x, xD.y); v1.w = pk2(xD.z, xD.w);
                *(uint4*)(st + r * 128 + (((seg*2    ) ^ (r & 7)) << 4)) = v0;
                *(uint4*)(st + r * 128 + (((seg*2 + 1) ^ (r & 7)) << 4)) = v1;
            } else if (wvalid) {
                const __half* wh = (const __half*)&wreg;
                #pragma unroll
                for (int t = 0; t < WIN; ++t) {
                    int k = wkb + t;
                    if ((unsigned)k < (unsigned)KTILE)
                        *(__half*)(st + wb * 128
                                   + ((((unsigned)k >> 3) ^ (wb & 7)) << 4)
                                   + ((k & 7) << 1)) = wh[t];
                }
            }
        }
    }

    // ---- epilogue: accumulate partials onto zero-initialized out ----
    #pragma unroll
    for (int a = 0; a < 2; ++a) {
        const int row = m0 + warp_m * 32 + a * 16 + (lane >> 2);
        #pragma unroll
        for (int bn = 0; bn < 8; ++bn) {
            const int col = warp_n * 64 + bn * 8 + (lane & 3) * 2;
            float* p0 = out + (size_t)row * OUTF + col;
            atomicAdd(p0,                acc[a][bn][0]);
            atomicAdd(p0 + 1,            acc[a][bn][1]);
            atomicAdd(p0 + 8 * OUTF,     acc[a][bn][2]);
            atomicAdd(p0 + 8 * OUTF + 1, acc[a][bn][3]);
        }
    }
}

// ============================================================================
extern "C" void kernel_launch(void* const* d_in, const int* in_sizes, int n_in,
                              void* d_out, int out_size) {
    const float* x  = (const float*)d_in[0];   // [4096, 256]
    const float* bw = (const float*)d_in[1];   // [256, 256]
    const float* sw = (const float*)d_in[2];   // [256, 256, 66]
    const float* sc = (const float*)d_in[3];   // [256, 256]
    float* out = (float*)d_out;                // [4096, 256] fp32

    static bool attr_done = false;
    if (!attr_done) {
        cudaFuncSetAttribute(kan_spline_gemm,
                             cudaFuncAttributeMaxDynamicSharedMemorySize,
                             3 * STAGE_B);
        attr_done = true;
    }

    cudaMemsetAsync(out, 0, (size_t)BQ * OUTF * sizeof(float));
    kan_scale_kernel<<<32, 256>>>(sc);
    kan_w2_kernel<<<OUTF, 256>>>(sw, bw);
    kan_win_kernel<<<dim3(BQ / 64, INF / 64), 256>>>(x);
    kan_spline_gemm<<<dim3(BQ / MT, KSPLIT), 512, 3 * STAGE_B>>>(x, out);
}